// round 1
// baseline (speedup 1.0000x reference)
#include <cuda_runtime.h>
#include <math.h>

#define BSZ 4096
#define NE  6
#define DF  1830
#define DPD 2086
#define DH  512

// ---- scratch (device globals: no allocations allowed) ----
__device__ float g_h0 [BSZ*DPD];   // frame_prev (0:1830) | INet out (1830:2086)
__device__ float g_ih1[BSZ*256];
__device__ float g_ih2[BSZ*256];
__device__ float g_gh1[BSZ*512];
__device__ float g_gh2[BSZ*256];
__device__ float g_om [BSZ*NE];
__device__ float g_e1 [BSZ*DH];
__device__ float g_e2 [BSZ*DH];
__device__ float g_e3 [BSZ*DH];
__device__ float g_hd [BSZ*DF];    // stacked head outputs [p330|t3|d297|v1200]

constexpr int BM = 128, BN = 64, BK = 16, TM = 8, TN = 4;  // 256 threads

__device__ __forceinline__ float elu1(float x) { return x > 0.f ? x : expm1f(x); }

// ---------------------------------------------------------------------------
// frame_prev assembly: pose6d(330) | transl(3) | verts(1200) | dists(297)
// ---------------------------------------------------------------------------
__global__ void assemble_frame(const float* __restrict__ rot,
                               const float* __restrict__ tr,
                               const float* __restrict__ verts,
                               const float* __restrict__ dists) {
    int idx = blockIdx.x * 256 + threadIdx.x;
    if (idx >= BSZ * DF) return;
    int b = idx / DF, c = idx % DF;
    float v;
    if (c < 330) {
        int j = c / 6, s = c % 6;
        int r = s >> 1, cc = s & 1;          // row-major 3x3, first two columns
        v = rot[b * 495 + j * 9 + r * 3 + cc];
    } else if (c < 333) v = tr[b * 3 + (c - 330)];
    else if (c < 1533)  v = verts[b * 1200 + (c - 333)];
    else                v = dists[b * 297 + (c - 1533)];
    g_h0[(size_t)b * DPD + c] = v;
}

// ---------------------------------------------------------------------------
// Generic SGEMM: C[M=4096, N] = act(A[M,K] @ B[K,N] + bias)
// CONCAT: A is (A | A2) split at K1 (for INet input concat)
// ---------------------------------------------------------------------------
template <bool CONCAT, bool DOELU>
__global__ void __launch_bounds__(256) sgemm(
    const float* __restrict__ A, int lda,
    const float* __restrict__ A2, int lda2, int K1,
    const float* __restrict__ B, const float* __restrict__ bias,
    float* __restrict__ C, int ldc, int N, int K)
{
    __shared__ float As[BK][BM + 4];
    __shared__ float Bs[BK][BN];
    const int rowBase = blockIdx.y * BM;
    const int colBase = blockIdx.x * BN;
    const int tid  = threadIdx.x;
    const int trow = (tid >> 4) * TM;
    const int tcol = (tid & 15) * TN;
    float acc[TM][TN] = {};
    for (int k0 = 0; k0 < K; k0 += BK) {
#pragma unroll
        for (int i = 0; i < 8; i++) {
            int idx = tid + i * 256;
            int r = idx >> 4, c = idx & 15;
            int k = k0 + c;
            float v = 0.f;
            if (k < K) {
                int row = rowBase + r;
                if (CONCAT)
                    v = (k < K1) ? A[(size_t)row * lda + k]
                                 : A2[(size_t)row * lda2 + (k - K1)];
                else
                    v = A[(size_t)row * lda + k];
            }
            As[c][r] = v;
        }
#pragma unroll
        for (int i = 0; i < 4; i++) {
            int idx = tid + i * 256;
            int r = idx >> 6, c = idx & 63;
            int k = k0 + r, n = colBase + c;
            Bs[r][c] = (k < K && n < N) ? B[(size_t)k * N + n] : 0.f;
        }
        __syncthreads();
#pragma unroll
        for (int kk = 0; kk < BK; kk++) {
            float4 a0 = *(const float4*)&As[kk][trow];
            float4 a1 = *(const float4*)&As[kk][trow + 4];
            float4 bv = *(const float4*)&Bs[kk][tcol];
            float aa[8] = {a0.x, a0.y, a0.z, a0.w, a1.x, a1.y, a1.z, a1.w};
            float bb[4] = {bv.x, bv.y, bv.z, bv.w};
#pragma unroll
            for (int i = 0; i < 8; i++)
#pragma unroll
                for (int j = 0; j < 4; j++) acc[i][j] += aa[i] * bb[j];
        }
        __syncthreads();
    }
#pragma unroll
    for (int i = 0; i < 8; i++) {
        size_t row = rowBase + trow + i;
#pragma unroll
        for (int j = 0; j < 4; j++) {
            int n = colBase + tcol + j;
            if (n < N) {
                float v = acc[i][j] + bias[n];
                if (DOELU) v = elu1(v);
                C[row * ldc + n] = v;
            }
        }
    }
}

// ---------------------------------------------------------------------------
// MoE GEMM: C = elu( sum_e omega[b,e] * (A @ W_e) + omega @ eb )
// omega folded into the A smem tile (scale at store), single accumulator.
// N is always 512 here (aligned); K may have a tail.
// ---------------------------------------------------------------------------
__global__ void __launch_bounds__(256) moe_gemm(
    const float* __restrict__ A, int lda,
    const float* __restrict__ W,      // [E, K, N]
    const float* __restrict__ eb,     // [E, N]
    const float* __restrict__ omega,  // [M, E]
    float* __restrict__ C, int N, int K)
{
    __shared__ float As[BK][BM + 4];
    __shared__ float Bs[BK][BN];
    __shared__ float omS[NE][BM];
    const int rowBase = blockIdx.y * BM;
    const int colBase = blockIdx.x * BN;
    const int tid = threadIdx.x;
    for (int idx = tid; idx < NE * BM; idx += 256) {
        int e = idx / BM, r = idx % BM;
        omS[e][r] = omega[(size_t)(rowBase + r) * NE + e];
    }
    __syncthreads();
    const int trow = (tid >> 4) * TM;
    const int tcol = (tid & 15) * TN;
    float acc[TM][TN] = {};
    for (int e = 0; e < NE; e++) {
        const float* Be = W + (size_t)e * K * N;
        for (int k0 = 0; k0 < K; k0 += BK) {
#pragma unroll
            for (int i = 0; i < 8; i++) {
                int idx = tid + i * 256;
                int r = idx >> 4, c = idx & 15;
                int k = k0 + c;
                float v = 0.f;
                if (k < K) v = A[(size_t)(rowBase + r) * lda + k] * omS[e][r];
                As[c][r] = v;
            }
#pragma unroll
            for (int i = 0; i < 4; i++) {
                int idx = tid + i * 256;
                int r = idx >> 6, c = idx & 63;
                int k = k0 + r;
                Bs[r][c] = (k < K) ? Be[(size_t)k * N + colBase + c] : 0.f;
            }
            __syncthreads();
#pragma unroll
            for (int kk = 0; kk < BK; kk++) {
                float4 a0 = *(const float4*)&As[kk][trow];
                float4 a1 = *(const float4*)&As[kk][trow + 4];
                float4 bv = *(const float4*)&Bs[kk][tcol];
                float aa[8] = {a0.x, a0.y, a0.z, a0.w, a1.x, a1.y, a1.z, a1.w};
                float bb[4] = {bv.x, bv.y, bv.z, bv.w};
#pragma unroll
                for (int i = 0; i < 8; i++)
#pragma unroll
                    for (int j = 0; j < 4; j++) acc[i][j] += aa[i] * bb[j];
            }
            __syncthreads();
        }
    }
#pragma unroll
    for (int j = 0; j < 4; j++) {
        int n = colBase + tcol + j;
        float w[NE];
#pragma unroll
        for (int e = 0; e < NE; e++) w[e] = eb[e * N + n];
#pragma unroll
        for (int i = 0; i < 8; i++) {
            float bsum = 0.f;
#pragma unroll
            for (int e = 0; e < NE; e++) bsum += omS[e][trow + i] * w[e];
            C[(size_t)(rowBase + trow + i) * N + n] = elu1(acc[i][j] + bsum);
        }
    }
}

// ---------------------------------------------------------------------------
// Stacked heads GEMM: [pw|tw|dw|vw] as one 512 -> 1830 GEMM into g_hd
// column layout: [0,330)=p  [330,333)=t  [333,630)=d  [630,1830)=v
// ---------------------------------------------------------------------------
__device__ __forceinline__ float head_w(const float* pw, const float* tw,
                                        const float* dw, const float* vw,
                                        int k, int n) {
    if (n < 330) return pw[k * 330 + n];
    if (n < 333) return tw[k * 3 + (n - 330)];
    if (n < 630) return dw[k * 297 + (n - 333)];
    return vw[(size_t)k * 1200 + (n - 630)];
}
__device__ __forceinline__ float head_b(const float* pb, const float* tb,
                                        const float* db, const float* vb, int n) {
    if (n < 330) return pb[n];
    if (n < 333) return tb[n - 330];
    if (n < 630) return db[n - 333];
    return vb[n - 630];
}

__global__ void __launch_bounds__(256) heads_gemm(
    const float* __restrict__ A,  // g_e3 [4096,512]
    const float* __restrict__ pw, const float* __restrict__ tw,
    const float* __restrict__ dw, const float* __restrict__ vw,
    const float* __restrict__ pb, const float* __restrict__ tb,
    const float* __restrict__ db, const float* __restrict__ vb,
    float* __restrict__ C)
{
    const int N = DF, K = DH;
    __shared__ float As[BK][BM + 4];
    __shared__ float Bs[BK][BN];
    const int rowBase = blockIdx.y * BM;
    const int colBase = blockIdx.x * BN;
    const int tid = threadIdx.x;
    const int trow = (tid >> 4) * TM;
    const int tcol = (tid & 15) * TN;
    float acc[TM][TN] = {};
    for (int k0 = 0; k0 < K; k0 += BK) {
#pragma unroll
        for (int i = 0; i < 8; i++) {
            int idx = tid + i * 256;
            int r = idx >> 4, c = idx & 15;
            As[c][r] = A[(size_t)(rowBase + r) * K + (k0 + c)];
        }
#pragma unroll
        for (int i = 0; i < 4; i++) {
            int idx = tid + i * 256;
            int r = idx >> 6, c = idx & 63;
            int n = colBase + c;
            Bs[r][c] = (n < N) ? head_w(pw, tw, dw, vw, k0 + r, n) : 0.f;
        }
        __syncthreads();
#pragma unroll
        for (int kk = 0; kk < BK; kk++) {
            float4 a0 = *(const float4*)&As[kk][trow];
            float4 a1 = *(const float4*)&As[kk][trow + 4];
            float4 bv = *(const float4*)&Bs[kk][tcol];
            float aa[8] = {a0.x, a0.y, a0.z, a0.w, a1.x, a1.y, a1.z, a1.w};
            float bb[4] = {bv.x, bv.y, bv.z, bv.w};
#pragma unroll
            for (int i = 0; i < 8; i++)
#pragma unroll
                for (int j = 0; j < 4; j++) acc[i][j] += aa[i] * bb[j];
        }
        __syncthreads();
    }
#pragma unroll
    for (int i = 0; i < 8; i++) {
        size_t row = rowBase + trow + i;
#pragma unroll
        for (int j = 0; j < 4; j++) {
            int n = colBase + tcol + j;
            if (n < N)
                C[row * DF + n] = acc[i][j] + head_b(pb, tb, db, vb, n);
        }
    }
}

// ---------------------------------------------------------------------------
// Gating layer 3 (256 -> 6) + softmax: one warp per row
// ---------------------------------------------------------------------------
__global__ void gate3_softmax(const float* __restrict__ H,
                              const float* __restrict__ W,   // [256,6]
                              const float* __restrict__ b,
                              float* __restrict__ om) {
    int warp = (blockIdx.x * blockDim.x + threadIdx.x) >> 5;
    int lane = threadIdx.x & 31;
    if (warp >= BSZ) return;
    float p[NE] = {};
    for (int k = lane; k < 256; k += 32) {
        float x = H[(size_t)warp * 256 + k];
#pragma unroll
        for (int e = 0; e < NE; e++) p[e] += x * W[k * NE + e];
    }
#pragma unroll
    for (int e = 0; e < NE; e++)
        for (int o = 16; o > 0; o >>= 1)
            p[e] += __shfl_down_sync(0xffffffffu, p[e], o);
    if (lane == 0) {
        float m = -1e30f;
#pragma unroll
        for (int e = 0; e < NE; e++) { p[e] += b[e]; m = fmaxf(m, p[e]); }
        float s = 0.f;
#pragma unroll
        for (int e = 0; e < NE; e++) { p[e] = expf(p[e] - m); s += p[e]; }
        float inv = 1.f / s;
#pragma unroll
        for (int e = 0; e < NE; e++) om[(size_t)warp * NE + e] = p[e] * inv;
    }
}

// ---------------------------------------------------------------------------
// Post-processing: crot2rotmat on p(330) -> pose out; copy t/d/v regions
// out layout: pose [0, 4096*495) | transl | dists | verts (flatten-concat)
// ---------------------------------------------------------------------------
__global__ void post_pose(const float* __restrict__ hd, float* __restrict__ out) {
    int idx = blockIdx.x * 256 + threadIdx.x;
    if (idx >= BSZ * 55) return;
    int b = idx / 55, j = idx % 55;
    const float* p = hd + (size_t)b * DF + j * 6;
    float a1x = p[0], a2x = p[1], a1y = p[2], a2y = p[3], a1z = p[4], a2z = p[5];
    float inv = rsqrtf(a1x * a1x + a1y * a1y + a1z * a1z);
    float b1x = a1x * inv, b1y = a1y * inv, b1z = a1z * inv;
    float d = b1x * a2x + b1y * a2y + b1z * a2z;
    float cx = a2x - d * b1x, cy = a2y - d * b1y, cz = a2z - d * b1z;
    float inv2 = rsqrtf(cx * cx + cy * cy + cz * cz);
    float b2x = cx * inv2, b2y = cy * inv2, b2z = cz * inv2;
    float b3x = b1y * b2z - b1z * b2y;
    float b3y = b1z * b2x - b1x * b2z;
    float b3z = b1x * b2y - b1y * b2x;
    float* o = out + (size_t)b * 495 + j * 9;   // columns = (b1,b2,b3), row-major 3x3
    o[0] = b1x; o[1] = b2x; o[2] = b3x;
    o[3] = b1y; o[4] = b2y; o[5] = b3y;
    o[6] = b1z; o[7] = b2z; o[8] = b3z;
}

__global__ void post_copy(const float* __restrict__ hd, float* __restrict__ out) {
    const size_t base_t = (size_t)BSZ * 495;
    const size_t base_d = base_t + (size_t)BSZ * 3;
    const size_t base_v = base_d + (size_t)BSZ * 297;
    int idx = blockIdx.x * 256 + threadIdx.x;
    if (idx >= BSZ * 1500) return;
    int b = idx / 1500, c = idx % 1500;
    const float* row = hd + (size_t)b * DF;
    if (c < 3)        out[base_t + (size_t)b * 3 + c]            = row[330 + c];
    else if (c < 300) out[base_d + (size_t)b * 297 + (c - 3)]    = row[333 + (c - 3)];
    else              out[base_v + (size_t)b * 1200 + (c - 300)] = row[630 + (c - 300)];
}

// ---------------------------------------------------------------------------
extern "C" void kernel_launch(void* const* d_in, const int* in_sizes, int n_in,
                              void* d_out, int out_size) {
    const float* rot   = (const float*)d_in[0];
    const float* tr    = (const float*)d_in[1];
    const float* verts = (const float*)d_in[2];
    const float* dists = (const float*)d_in[3];
    const float* bps   = (const float*)d_in[4];
    const float* ogt   = (const float*)d_in[5];
    const float* iw1 = (const float*)d_in[6];  const float* ib1 = (const float*)d_in[7];
    const float* iw2 = (const float*)d_in[8];  const float* ib2 = (const float*)d_in[9];
    const float* iw3 = (const float*)d_in[10]; const float* ib3 = (const float*)d_in[11];
    const float* gw1 = (const float*)d_in[12]; const float* gb1 = (const float*)d_in[13];
    const float* gw2 = (const float*)d_in[14]; const float* gb2 = (const float*)d_in[15];
    const float* gw3 = (const float*)d_in[16]; const float* gb3 = (const float*)d_in[17];
    const float* ew1 = (const float*)d_in[18]; const float* eb1 = (const float*)d_in[19];
    const float* ew2 = (const float*)d_in[20]; const float* eb2 = (const float*)d_in[21];
    const float* ew3 = (const float*)d_in[22]; const float* eb3 = (const float*)d_in[23];
    const float* pw  = (const float*)d_in[24]; const float* pb  = (const float*)d_in[25];
    const float* tw  = (const float*)d_in[26]; const float* tb  = (const float*)d_in[27];
    const float* vw  = (const float*)d_in[28]; const float* vb  = (const float*)d_in[29];
    const float* dw  = (const float*)d_in[30]; const float* db  = (const float*)d_in[31];
    float* out = (float*)d_out;

    float *h0, *ih1, *ih2, *gh1, *gh2, *om, *e1, *e2, *e3, *hd;
    cudaGetSymbolAddress((void**)&h0,  g_h0);
    cudaGetSymbolAddress((void**)&ih1, g_ih1);
    cudaGetSymbolAddress((void**)&ih2, g_ih2);
    cudaGetSymbolAddress((void**)&gh1, g_gh1);
    cudaGetSymbolAddress((void**)&gh2, g_gh2);
    cudaGetSymbolAddress((void**)&om,  g_om);
    cudaGetSymbolAddress((void**)&e1,  g_e1);
    cudaGetSymbolAddress((void**)&e2,  g_e2);
    cudaGetSymbolAddress((void**)&e3,  g_e3);
    cudaGetSymbolAddress((void**)&hd,  g_hd);

    // frame_prev assembly
    assemble_frame<<<(BSZ * DF + 255) / 256, 256>>>(rot, tr, verts, dists);

    const int GY = BSZ / BM;  // 32
    // INet: (bps|ogt) 1027 -> 256 -> 256 -> 256 (last into h0 cols [1830,2086))
    sgemm<true,  true><<<dim3(4, GY), 256>>>(bps, 1024, ogt, 3, 1024, iw1, ib1, ih1, 256, 256, 1027);
    sgemm<false, true><<<dim3(4, GY), 256>>>(ih1, 256, nullptr, 0, 0, iw2, ib2, ih2, 256, 256, 256);
    sgemm<false, true><<<dim3(4, GY), 256>>>(ih2, 256, nullptr, 0, 0, iw3, ib3, h0 + 1830, DPD, 256, 256);
    // Gating: 1830 -> 512 -> 256 -> 6 + softmax
    sgemm<false, true><<<dim3(8, GY), 256>>>(h0, DPD, nullptr, 0, 0, gw1, gb1, gh1, 512, 512, 1830);
    sgemm<false, true><<<dim3(4, GY), 256>>>(gh1, 512, nullptr, 0, 0, gw2, gb2, gh2, 256, 256, 512);
    gate3_softmax<<<BSZ / 8, 256>>>(gh2, gw3, gb3, om);
    // Experts (blend fused into A-tile)
    moe_gemm<<<dim3(8, GY), 256>>>(h0, DPD, ew1, eb1, om, e1, DH, DPD);
    moe_gemm<<<dim3(8, GY), 256>>>(e1, DH,  ew2, eb2, om, e2, DH, DH);
    moe_gemm<<<dim3(8, GY), 256>>>(e2, DH,  ew3, eb3, om, e3, DH, DH);
    // Heads (stacked) + post-processing
    heads_gemm<<<dim3((DF + BN - 1) / BN, GY), 256>>>(e3, pw, tw, dw, vw, pb, tb, db, vb, hd);
    post_pose<<<(BSZ * 55 + 255) / 256, 256>>>(hd, out);
    post_copy<<<(BSZ * 1500 + 255) / 256, 256>>>(hd, out);
}

// round 3
// speedup vs baseline: 1.5233x; 1.5233x over previous
#include <cuda_runtime.h>
#include <cuda_bf16.h>
#include <math.h>
#include <stdint.h>

#define BSZ 4096
#define NE  6
#define DF  1830
#define DPD 2086
#define DH  512

// Kpad: multiples of 32
#define KP_I1 1056
#define KP_G1 1856
#define KP_E1 2112

// ---------------- scratch (device globals; no allocs allowed) ----------------
__device__ float g_h0 [BSZ*DPD];
__device__ float g_ih1[BSZ*256];
__device__ float g_ih2[BSZ*256];
__device__ float g_gh1[BSZ*512];
__device__ float g_gh2[BSZ*256];
__device__ float g_om [BSZ*NE];
__device__ float g_e1 [BSZ*DH];
__device__ float g_e2 [BSZ*DH];
__device__ float g_e3 [BSZ*DH];
__device__ float g_hd [BSZ*DF];

__device__ __nv_bfloat16 s_iw1h[256*KP_I1],  s_iw1m[256*KP_I1];
__device__ __nv_bfloat16 s_iw2h[256*256],    s_iw2m[256*256];
__device__ __nv_bfloat16 s_iw3h[256*256],    s_iw3m[256*256];
__device__ __nv_bfloat16 s_gw1h[512*KP_G1],  s_gw1m[512*KP_G1];
__device__ __nv_bfloat16 s_gw2h[256*512],    s_gw2m[256*512];
__device__ __nv_bfloat16 s_ew1h[(size_t)NE*512*KP_E1], s_ew1m[(size_t)NE*512*KP_E1];
__device__ __nv_bfloat16 s_ew2h[(size_t)NE*512*512],   s_ew2m[(size_t)NE*512*512];
__device__ __nv_bfloat16 s_ew3h[(size_t)NE*512*512],   s_ew3m[(size_t)NE*512*512];
__device__ __nv_bfloat16 s_hwh[(size_t)DF*512],        s_hwm[(size_t)DF*512];
__device__ float g_hbias[DF];

__device__ __forceinline__ float elu1(float x) { return x > 0.f ? x : expm1f(x); }

__device__ __forceinline__ uint32_t smem_u32(const void* p) {
    uint32_t a;
    asm("{ .reg .u64 t; cvta.to.shared.u64 t, %1; cvt.u32.u64 %0, t; }" : "=r"(a) : "l"(p));
    return a;
}
__device__ __forceinline__ uint32_t pack_split(float x0, float x1, uint32_t& mid) {
    __nv_bfloat16 h0 = __float2bfloat16(x0);
    __nv_bfloat16 h1 = __float2bfloat16(x1);
    float r0 = x0 - __bfloat162float(h0);
    float r1 = x1 - __bfloat162float(h1);
    __nv_bfloat16 m0 = __float2bfloat16(r0);
    __nv_bfloat16 m1 = __float2bfloat16(r1);
    mid = ((uint32_t)__bfloat16_as_ushort(m1) << 16) | __bfloat16_as_ushort(m0);
    return ((uint32_t)__bfloat16_as_ushort(h1) << 16) | __bfloat16_as_ushort(h0);
}
__device__ __forceinline__ void ldm4(uint32_t& r0, uint32_t& r1, uint32_t& r2, uint32_t& r3,
                                     uint32_t addr) {
    asm volatile("ldmatrix.sync.aligned.m8n8.x4.shared.b16 {%0,%1,%2,%3}, [%4];"
                 : "=r"(r0), "=r"(r1), "=r"(r2), "=r"(r3) : "r"(addr));
}
__device__ __forceinline__ void mma16816(float* d, uint32_t a0, uint32_t a1, uint32_t a2,
                                         uint32_t a3, uint32_t b0, uint32_t b1) {
    asm volatile("mma.sync.aligned.m16n8k16.row.col.f32.bf16.bf16.f32 "
                 "{%0,%1,%2,%3}, {%4,%5,%6,%7}, {%8,%9}, {%0,%1,%2,%3};"
                 : "+f"(d[0]), "+f"(d[1]), "+f"(d[2]), "+f"(d[3])
                 : "r"(a0), "r"(a1), "r"(a2), "r"(a3), "r"(b0), "r"(b1));
}

// ---------------- smem layout ----------------
constexpr int OFF_A32 = 0;                  // 128 x 36 fp32 = 18432
constexpr int OFF_AH  = 18432;              // 128 x 80B
constexpr int OFF_AM  = 28672;
constexpr int OFF_BH  = 38912;
constexpr int OFF_BM  = 49152;
constexpr int OFF_OM  = 59392;              // NE*128*4 = 3072
constexpr int SMEM_BYTES = 62464;

// ---------------------------------------------------------------------------
// bf16x3 split GEMM on mma.sync (HMMA):
//   C[4096, Nw] = act( sum_e omega[:,e] * (A @ W_e) + bias )
// Wh/Wm pre-split, transposed [E][Nw][Kpad] bf16. A fp32 (optional concat A2).
// ---------------------------------------------------------------------------
__global__ void __launch_bounds__(256) gemm_mma(
    const float* __restrict__ A, int lda,
    const float* __restrict__ A2, int K1,
    const __nv_bfloat16* __restrict__ Wh, const __nv_bfloat16* __restrict__ Wm,
    const float* __restrict__ omega,
    const float* __restrict__ bias,
    float* __restrict__ C, int ldc,
    int Nw, int K, int Kpad, int E, int blend, int doElu)
{
    extern __shared__ char smem[];
    const uint32_t sb = smem_u32(smem);
    float* A32 = (float*)(smem + OFF_A32);
    float* omS = (float*)(smem + OFF_OM);

    const int tid  = threadIdx.x;
    const int lane = tid & 31, warp = tid >> 5;
    const int m_base = (warp & 3) * 32;
    const int n_base = (warp >> 2) * 64;
    const int rowBase = blockIdx.y * 128;
    const int colBase = blockIdx.x * 128;

    for (int i = tid; i < E * 128; i += 256) {
        int e = i >> 7, r = i & 127;
        omS[e * 128 + r] = omega ? omega[(size_t)(rowBase + r) * E + e] : 1.0f;
    }

    float acc[2][8][4];
#pragma unroll
    for (int a = 0; a < 2; a++)
#pragma unroll
        for (int b = 0; b < 8; b++)
#pragma unroll
            for (int c = 0; c < 4; c++) acc[a][b][c] = 0.f;

    const int r  = tid >> 1, h = tid & 1;        // staging: row, k-half
    const int row = rowBase + r;
    const int lm = lane & 15, lc = lane >> 4;    // ldmatrix A mapping
    const int g  = lane >> 3;
    const int b_row = ((g >> 1) << 3) + (lane & 7);
    const int b_koff = (g & 1) << 4;

    const int nChunks = Kpad >> 5;
    for (int kc = 0; kc < nChunks; kc++) {
        const int k0 = kc << 5;
        // ---- fp32 A chunk into smem (shared across experts) ----
        {
            float v[16];
#pragma unroll
            for (int j = 0; j < 16; j++) {
                int k = k0 + h * 16 + j;
                float x = 0.f;
                if (k < K) x = (A2 && k >= K1) ? A2[row * 3 + (k - K1)]
                                               : A[(size_t)row * lda + k];
                v[j] = x;
            }
#pragma unroll
            for (int j = 0; j < 16; j++) A32[r * 36 + h * 16 + j] = v[j];
        }
        __syncthreads();

        for (int e = 0; e < E; e++) {
            // ---- stage: scale+split A; cp.async B (pre-split) ----
            {
                const float w = omS[e * 128 + r];
                const float4* av = (const float4*)(A32 + r * 36 + h * 16);
                uint32_t hi[8], mi[8];
#pragma unroll
                for (int u = 0; u < 4; u++) {
                    float4 x = av[u];
                    hi[2*u]   = pack_split(x.x * w, x.y * w, mi[2*u]);
                    hi[2*u+1] = pack_split(x.z * w, x.w * w, mi[2*u+1]);
                }
                char* dH = smem + OFF_AH + r * 80 + h * 32;
                char* dM = smem + OFF_AM + r * 80 + h * 32;
                *(uint4*)dH        = make_uint4(hi[0], hi[1], hi[2], hi[3]);
                *(uint4*)(dH + 16) = make_uint4(hi[4], hi[5], hi[6], hi[7]);
                *(uint4*)dM        = make_uint4(mi[0], mi[1], mi[2], mi[3]);
                *(uint4*)(dM + 16) = make_uint4(mi[4], mi[5], mi[6], mi[7]);
            }
#pragma unroll
            for (int q = 0; q < 4; q++) {
                int c = tid + q * 256;          // 0..1023
                int bufsel = c >> 9;
                int rem = c & 511;
                int n = rem >> 2, j = rem & 3;
                int gn = colBase + n;
                const __nv_bfloat16* W = bufsel ? Wm : Wh;
                const char* src = (const char*)(W + ((size_t)e * Nw + (gn < Nw ? gn : 0)) * Kpad + k0) + j * 16;
                uint32_t dst = sb + (bufsel ? OFF_BM : OFF_BH) + n * 80 + j * 16;
                int sz = (gn < Nw) ? 16 : 0;
                asm volatile("cp.async.cg.shared.global [%0], [%1], 16, %2;"
                             :: "r"(dst), "l"(src), "r"(sz));
            }
            asm volatile("cp.async.commit_group;");
            asm volatile("cp.async.wait_group 0;");
            __syncthreads();

            // ---- mma: 3 split terms ----
#pragma unroll
            for (int term = 0; term < 3; term++) {
                uint32_t aB = sb + ((term == 2) ? OFF_AM : OFF_AH);
                uint32_t bB = sb + ((term == 1) ? OFF_BM : OFF_BH);
#pragma unroll
                for (int kh = 0; kh < 2; kh++) {
                    uint32_t af[2][4];
#pragma unroll
                    for (int mi2 = 0; mi2 < 2; mi2++)
                        ldm4(af[mi2][0], af[mi2][1], af[mi2][2], af[mi2][3],
                             aB + (m_base + mi2 * 16 + lm) * 80 + kh * 32 + lc * 16);
#pragma unroll
                    for (int ni = 0; ni < 4; ni++) {
                        uint32_t b0, b1, b2, b3;
                        ldm4(b0, b1, b2, b3,
                             bB + (n_base + ni * 16 + b_row) * 80 + kh * 32 + b_koff);
#pragma unroll
                        for (int mi2 = 0; mi2 < 2; mi2++) {
                            mma16816(acc[mi2][2*ni],   af[mi2][0], af[mi2][1], af[mi2][2], af[mi2][3], b0, b1);
                            mma16816(acc[mi2][2*ni+1], af[mi2][0], af[mi2][1], af[mi2][2], af[mi2][3], b2, b3);
                        }
                    }
                }
            }
            __syncthreads();
        }
    }

    // ---- epilogue ----
#pragma unroll
    for (int mi2 = 0; mi2 < 2; mi2++) {
        int rA = m_base + mi2 * 16 + (lane >> 2);
        int rB = rA + 8;
#pragma unroll
        for (int nj = 0; nj < 8; nj++) {
            int n = colBase + n_base + nj * 8 + ((lane & 3) << 1);
            if (n >= Nw) continue;
            float bs0, bs1;
            if (blend) {
                bs0 = bs1 = 0.f;
                for (int e = 0; e < NE && e < E; e++) {
                    float be0 = bias[e * Nw + n], be1 = bias[e * Nw + n + 1];
                    bs0 += omS[e * 128 + rA] * be0;
                    bs1 += omS[e * 128 + rA] * be1;
                }
            } else { bs0 = bias[n]; bs1 = bias[n + 1]; }
            float v0 = acc[mi2][nj][0] + bs0;
            float v1 = acc[mi2][nj][1] + bs1;
            if (doElu) { v0 = elu1(v0); v1 = elu1(v1); }
            *(float2*)&C[(size_t)(rowBase + rA) * ldc + n] = make_float2(v0, v1);
            float bs0b, bs1b;
            if (blend) {
                bs0b = bs1b = 0.f;
                for (int e = 0; e < NE && e < E; e++) {
                    bs0b += omS[e * 128 + rB] * bias[e * Nw + n];
                    bs1b += omS[e * 128 + rB] * bias[e * Nw + n + 1];
                }
            } else { bs0b = bs0 - acc[mi2][nj][0] - 0.f, bs0b = bias[n], bs1b = bias[n + 1]; }
            float v2 = acc[mi2][nj][2] + bs0b;
            float v3 = acc[mi2][nj][3] + bs1b;
            if (doElu) { v2 = elu1(v2); v3 = elu1(v3); }
            *(float2*)&C[(size_t)(rowBase + rB) * ldc + n] = make_float2(v2, v3);
        }
    }
}

// ---------------------------------------------------------------------------
// Weight prep: transpose [K,N] fp32 -> [N,Kpad] bf16 hi/mid (zero pad)
// ---------------------------------------------------------------------------
__global__ void prep_split(const float* __restrict__ W, __nv_bfloat16* __restrict__ oh,
                           __nv_bfloat16* __restrict__ om_, int K, int Nw, int Kpad) {
    __shared__ float t[32][33];
    int e = blockIdx.z;
    const float* Ws = W + (size_t)e * K * Nw;
    __nv_bfloat16* po = oh  + (size_t)e * Nw * Kpad;
    __nv_bfloat16* pm = om_ + (size_t)e * Nw * Kpad;
    int k0 = blockIdx.x * 32, n0 = blockIdx.y * 32;
    int tx = threadIdx.x, ty = threadIdx.y;
#pragma unroll
    for (int i = 0; i < 4; i++) {
        int kk = k0 + ty + i * 8, nn = n0 + tx;
        t[ty + i * 8][tx] = (kk < K && nn < Nw) ? Ws[(size_t)kk * Nw + nn] : 0.f;
    }
    __syncthreads();
#pragma unroll
    for (int i = 0; i < 4; i++) {
        int nn = n0 + ty + i * 8, kk = k0 + tx;
        if (nn < Nw) {
            float x = t[tx][ty + i * 8];
            __nv_bfloat16 hh = __float2bfloat16(x);
            __nv_bfloat16 mm = __float2bfloat16(x - __bfloat162float(hh));
            po[(size_t)nn * Kpad + kk] = hh;
            pm[(size_t)nn * Kpad + kk] = mm;
        }
    }
}

__device__ __forceinline__ float head_w(const float* pw, const float* tw,
                                        const float* dw, const float* vw, int k, int n) {
    if (n < 330) return pw[k * 330 + n];
    if (n < 333) return tw[k * 3 + (n - 330)];
    if (n < 630) return dw[k * 297 + (n - 333)];
    return vw[(size_t)k * 1200 + (n - 630)];
}
__global__ void prep_heads(const float* pw, const float* tw, const float* dw, const float* vw,
                           __nv_bfloat16* oh, __nv_bfloat16* om_) {
    __shared__ float t[32][33];
    int k0 = blockIdx.x * 32, n0 = blockIdx.y * 32;
    int tx = threadIdx.x, ty = threadIdx.y;
#pragma unroll
    for (int i = 0; i < 4; i++) {
        int kk = k0 + ty + i * 8, nn = n0 + tx;
        t[ty + i * 8][tx] = (kk < 512 && nn < DF) ? head_w(pw, tw, dw, vw, kk, nn) : 0.f;
    }
    __syncthreads();
#pragma unroll
    for (int i = 0; i < 4; i++) {
        int nn = n0 + ty + i * 8, kk = k0 + tx;
        if (nn < DF) {
            float x = t[tx][ty + i * 8];
            __nv_bfloat16 hh = __float2bfloat16(x);
            __nv_bfloat16 mm = __float2bfloat16(x - __bfloat162float(hh));
            oh[(size_t)nn * 512 + kk] = hh;
            om_[(size_t)nn * 512 + kk] = mm;
        }
    }
}
__global__ void prep_hbias(const float* pb, const float* tb, const float* db, const float* vb,
                           float* out) {
    int n = blockIdx.x * 256 + threadIdx.x;
    if (n >= DF) return;
    float v;
    if (n < 330) v = pb[n];
    else if (n < 333) v = tb[n - 330];
    else if (n < 630) v = db[n - 333];
    else v = vb[n - 630];
    out[n] = v;
}

// ---------------------------------------------------------------------------
__global__ void assemble_frame(const float* __restrict__ rot, const float* __restrict__ tr,
                               const float* __restrict__ verts, const float* __restrict__ dists) {
    int idx = blockIdx.x * 256 + threadIdx.x;
    if (idx >= BSZ * DF) return;
    int b = idx / DF, c = idx % DF;
    float v;
    if (c < 330) {
        int j = c / 6, s = c % 6;
        v = rot[b * 495 + j * 9 + (s >> 1) * 3 + (s & 1)];
    } else if (c < 333) v = tr[b * 3 + (c - 330)];
    else if (c < 1533)  v = verts[b * 1200 + (c - 333)];
    else                v = dists[b * 297 + (c - 1533)];
    g_h0[(size_t)b * DPD + c] = v;
}

__global__ void gate3_softmax(const float* __restrict__ H, const float* __restrict__ W,
                              const float* __restrict__ b, float* __restrict__ om) {
    int warp = (blockIdx.x * blockDim.x + threadIdx.x) >> 5;
    int lane = threadIdx.x & 31;
    if (warp >= BSZ) return;
    float p[NE] = {};
    for (int k = lane; k < 256; k += 32) {
        float x = H[(size_t)warp * 256 + k];
#pragma unroll
        for (int e = 0; e < NE; e++) p[e] += x * W[k * NE + e];
    }
#pragma unroll
    for (int e = 0; e < NE; e++)
        for (int o = 16; o > 0; o >>= 1) p[e] += __shfl_down_sync(0xffffffffu, p[e], o);
    if (lane == 0) {
        float m = -1e30f;
#pragma unroll
        for (int e = 0; e < NE; e++) { p[e] += b[e]; m = fmaxf(m, p[e]); }
        float s = 0.f;
#pragma unroll
        for (int e = 0; e < NE; e++) { p[e] = expf(p[e] - m); s += p[e]; }
        float inv = 1.f / s;
#pragma unroll
        for (int e = 0; e < NE; e++) om[(size_t)warp * NE + e] = p[e] * inv;
    }
}

__global__ void post_pose(const float* __restrict__ hd, float* __restrict__ out) {
    int idx = blockIdx.x * 256 + threadIdx.x;
    if (idx >= BSZ * 55) return;
    int b = idx / 55, j = idx % 55;
    const float* p = hd + (size_t)b * DF + j * 6;
    float a1x = p[0], a2x = p[1], a1y = p[2], a2y = p[3], a1z = p[4], a2z = p[5];
    float inv = rsqrtf(a1x * a1x + a1y * a1y + a1z * a1z);
    float b1x = a1x * inv, b1y = a1y * inv, b1z = a1z * inv;
    float d = b1x * a2x + b1y * a2y + b1z * a2z;
    float cx = a2x - d * b1x, cy = a2y - d * b1y, cz = a2z - d * b1z;
    float inv2 = rsqrtf(cx * cx + cy * cy + cz * cz);
    float b2x = cx * inv2, b2y = cy * inv2, b2z = cz * inv2;
    float b3x = b1y * b2z - b1z * b2y;
    float b3y = b1z * b2x - b1x * b2z;
    float b3z = b1x * b2y - b1y * b2x;
    float* o = out + (size_t)b * 495 + j * 9;
    o[0] = b1x; o[1] = b2x; o[2] = b3x;
    o[3] = b1y; o[4] = b2y; o[5] = b3y;
    o[6] = b1z; o[7] = b2z; o[8] = b3z;
}

__global__ void post_copy(const float* __restrict__ hd, float* __restrict__ out) {
    const size_t base_t = (size_t)BSZ * 495;
    const size_t base_d = base_t + (size_t)BSZ * 3;
    const size_t base_v = base_d + (size_t)BSZ * 297;
    int idx = blockIdx.x * 256 + threadIdx.x;
    if (idx >= BSZ * 1500) return;
    int b = idx / 1500, c = idx % 1500;
    const float* row = hd + (size_t)b * DF;
    if (c < 3)        out[base_t + (size_t)b * 3 + c]            = row[330 + c];
    else if (c < 300) out[base_d + (size_t)b * 297 + (c - 3)]    = row[333 + (c - 3)];
    else              out[base_v + (size_t)b * 1200 + (c - 300)] = row[630 + (c - 300)];
}

// ---------------------------------------------------------------------------
extern "C" void kernel_launch(void* const* d_in, const int* in_sizes, int n_in,
                              void* d_out, int out_size) {
    const float* rot   = (const float*)d_in[0];
    const float* tr    = (const float*)d_in[1];
    const float* verts = (const float*)d_in[2];
    const float* dists = (const float*)d_in[3];
    const float* bps   = (const float*)d_in[4];
    const float* ogt   = (const float*)d_in[5];
    const float* iw1 = (const float*)d_in[6];  const float* ib1 = (const float*)d_in[7];
    const float* iw2 = (const float*)d_in[8];  const float* ib2 = (const float*)d_in[9];
    const float* iw3 = (const float*)d_in[10]; const float* ib3 = (const float*)d_in[11];
    const float* gw1 = (const float*)d_in[12]; const float* gb1 = (const float*)d_in[13];
    const float* gw2 = (const float*)d_in[14]; const float* gb2 = (const float*)d_in[15];
    const float* gw3 = (const float*)d_in[16]; const float* gb3 = (const float*)d_in[17];
    const float* ew1 = (const float*)d_in[18]; const float* eb1 = (const float*)d_in[19];
    const float* ew2 = (const float*)d_in[20]; const float* eb2 = (const float*)d_in[21];
    const float* ew3 = (const float*)d_in[22]; const float* eb3 = (const float*)d_in[23];
    const float* pw  = (const float*)d_in[24]; const float* pb  = (const float*)d_in[25];
    const float* tw  = (const float*)d_in[26]; const float* tb  = (const float*)d_in[27];
    const float* vw  = (const float*)d_in[28]; const float* vb  = (const float*)d_in[29];
    const float* dw  = (const float*)d_in[30]; const float* db  = (const float*)d_in[31];
    float* out = (float*)d_out;

    cudaFuncSetAttribute(gemm_mma, cudaFuncAttributeMaxDynamicSharedMemorySize, SMEM_BYTES);

    float *h0, *ih1, *ih2, *gh1, *gh2, *om, *e1, *e2, *e3, *hd, *hbias;
    cudaGetSymbolAddress((void**)&h0,  g_h0);
    cudaGetSymbolAddress((void**)&ih1, g_ih1);
    cudaGetSymbolAddress((void**)&ih2, g_ih2);
    cudaGetSymbolAddress((void**)&gh1, g_gh1);
    cudaGetSymbolAddress((void**)&gh2, g_gh2);
    cudaGetSymbolAddress((void**)&om,  g_om);
    cudaGetSymbolAddress((void**)&e1,  g_e1);
    cudaGetSymbolAddress((void**)&e2,  g_e2);
    cudaGetSymbolAddress((void**)&e3,  g_e3);
    cudaGetSymbolAddress((void**)&hd,  g_hd);
    cudaGetSymbolAddress((void**)&hbias, g_hbias);
    __nv_bfloat16 *iw1h,*iw1m,*iw2h,*iw2m,*iw3h,*iw3m,*gw1h,*gw1m,*gw2h,*gw2m;
    __nv_bfloat16 *ew1h,*ew1m,*ew2h,*ew2m,*ew3h,*ew3m,*hwh,*hwm;
    cudaGetSymbolAddress((void**)&iw1h, s_iw1h); cudaGetSymbolAddress((void**)&iw1m, s_iw1m);
    cudaGetSymbolAddress((void**)&iw2h, s_iw2h); cudaGetSymbolAddress((void**)&iw2m, s_iw2m);
    cudaGetSymbolAddress((void**)&iw3h, s_iw3h); cudaGetSymbolAddress((void**)&iw3m, s_iw3m);
    cudaGetSymbolAddress((void**)&gw1h, s_gw1h); cudaGetSymbolAddress((void**)&gw1m, s_gw1m);
    cudaGetSymbolAddress((void**)&gw2h, s_gw2h); cudaGetSymbolAddress((void**)&gw2m, s_gw2m);
    cudaGetSymbolAddress((void**)&ew1h, s_ew1h); cudaGetSymbolAddress((void**)&ew1m, s_ew1m);
    cudaGetSymbolAddress((void**)&ew2h, s_ew2h); cudaGetSymbolAddress((void**)&ew2m, s_ew2m);
    cudaGetSymbolAddress((void**)&ew3h, s_ew3h); cudaGetSymbolAddress((void**)&ew3m, s_ew3m);
    cudaGetSymbolAddress((void**)&hwh,  s_hwh);  cudaGetSymbolAddress((void**)&hwm,  s_hwm);

    dim3 tb32(32, 8);
    prep_split<<<dim3(KP_I1/32, 8, 1),  tb32>>>(iw1, iw1h, iw1m, 1027, 256, KP_I1);
    prep_split<<<dim3(8, 8, 1),         tb32>>>(iw2, iw2h, iw2m, 256, 256, 256);
    prep_split<<<dim3(8, 8, 1),         tb32>>>(iw3, iw3h, iw3m, 256, 256, 256);
    prep_split<<<dim3(KP_G1/32, 16, 1), tb32>>>(gw1, gw1h, gw1m, 1830, 512, KP_G1);
    prep_split<<<dim3(16, 8, 1),        tb32>>>(gw2, gw2h, gw2m, 512, 256, 512);
    prep_split<<<dim3(KP_E1/32, 16, NE),tb32>>>(ew1, ew1h, ew1m, 2086, 512, KP_E1);
    prep_split<<<dim3(16, 16, NE),      tb32>>>(ew2, ew2h, ew2m, 512, 512, 512);
    prep_split<<<dim3(16, 16, NE),      tb32>>>(ew3, ew3h, ew3m, 512, 512, 512);
    prep_heads<<<dim3(16, 58, 1),       tb32>>>(pw, tw, dw, vw, hwh, hwm);
    prep_hbias<<<8, 256>>>(pb, tb, db, vb, hbias);

    assemble_frame<<<(BSZ * DF + 255) / 256, 256>>>(rot, tr, verts, dists);

    const int GY = BSZ / 128;  // 32
    gemm_mma<<<dim3(2, GY), 256, SMEM_BYTES>>>(bps, 1024, ogt, 1024, iw1h, iw1m, nullptr, ib1,
                                               ih1, 256, 256, 1027, KP_I1, 1, 0, 1);
    gemm_mma<<<dim3(2, GY), 256, SMEM_BYTES>>>(ih1, 256, nullptr, 0, iw2h, iw2m, nullptr, ib2,
                                               ih2, 256, 256, 256, 256, 1, 0, 1);
    gemm_mma<<<dim3(2, GY), 256, SMEM_BYTES>>>(ih2, 256, nullptr, 0, iw3h, iw3m, nullptr, ib3,
                                               h0 + 1830, DPD, 256, 256, 256, 1, 0, 1);
    gemm_mma<<<dim3(4, GY), 256, SMEM_BYTES>>>(h0, DPD, nullptr, 0, gw1h, gw1m, nullptr, gb1,
                                               gh1, 512, 512, 1830, KP_G1, 1, 0, 1);
    gemm_mma<<<dim3(2, GY), 256, SMEM_BYTES>>>(gh1, 512, nullptr, 0, gw2h, gw2m, nullptr, gb2,
                                               gh2, 256, 256, 512, 512, 1, 0, 1);
    gate3_softmax<<<BSZ / 8, 256>>>(gh2, gw3, gb3, om);
    gemm_mma<<<dim3(4, GY), 256, SMEM_BYTES>>>(h0, DPD, nullptr, 0, ew1h, ew1m, om, eb1,
                                               e1, DH, DH, DPD, KP_E1, NE, 1, 1);
    gemm_mma<<<dim3(4, GY), 256, SMEM_BYTES>>>(e1, DH, nullptr, 0, ew2h, ew2m, om, eb2,
                                               e2, DH, DH, DH, DH, NE, 1, 1);
    gemm_mma<<<dim3(4, GY), 256, SMEM_BYTES>>>(e2, DH, nullptr, 0, ew3h, ew3m, om, eb3,
                                               e3, DH, DH, DH, DH, NE, 1, 1);
    gemm_mma<<<dim3(15, GY), 256, SMEM_BYTES>>>(e3, DH, nullptr, 0, hwh, hwm, nullptr, hbias,
                                                hd, DF, DF, DH, DH, 1, 0, 0);
    post_pose<<<(BSZ * 55 + 255) / 256, 256>>>(hd, out);
    post_copy<<<(BSZ * 1500 + 255) / 256, 256>>>(hd, out);
}

// round 4
// speedup vs baseline: 1.8992x; 1.2468x over previous
#include <cuda_runtime.h>
#include <cuda_bf16.h>
#include <math.h>
#include <stdint.h>

#define BSZ 4096
#define NE  6
#define DF  1830
#define DPD 2086
#define DH  512

// Kpad: multiples of 32
#define KP_I1 1056
#define KP_G1 1856
#define KP_E1 2112

// ---------------- scratch (device globals; no allocs allowed) ----------------
__device__ float g_h0 [BSZ*DPD];
__device__ float g_ih1[BSZ*256];
__device__ float g_ih2[BSZ*256];
__device__ float g_gh1[BSZ*512];
__device__ float g_gh2[BSZ*256];
__device__ float g_om [BSZ*NE];
__device__ float g_e1 [BSZ*DH];
__device__ float g_e2 [BSZ*DH];
__device__ float g_e3 [BSZ*DH];
__device__ float g_hd [BSZ*DF];

__device__ __nv_bfloat16 s_iw1h[256*KP_I1],  s_iw1m[256*KP_I1];
__device__ __nv_bfloat16 s_iw2h[256*256],    s_iw2m[256*256];
__device__ __nv_bfloat16 s_iw3h[256*256],    s_iw3m[256*256];
__device__ __nv_bfloat16 s_gw1h[512*KP_G1],  s_gw1m[512*KP_G1];
__device__ __nv_bfloat16 s_gw2h[256*512],    s_gw2m[256*512];
__device__ __nv_bfloat16 s_ew1h[(size_t)NE*512*KP_E1], s_ew1m[(size_t)NE*512*KP_E1];
__device__ __nv_bfloat16 s_ew2h[(size_t)NE*512*512],   s_ew2m[(size_t)NE*512*512];
__device__ __nv_bfloat16 s_ew3h[(size_t)NE*512*512],   s_ew3m[(size_t)NE*512*512];
__device__ __nv_bfloat16 s_hwh[(size_t)DF*512],        s_hwm[(size_t)DF*512];
__device__ float g_hbias[DF];

__device__ __forceinline__ float elu1(float x) { return x > 0.f ? x : expm1f(x); }

__device__ __forceinline__ uint32_t smem_u32(const void* p) {
    uint32_t a;
    asm("{ .reg .u64 t; cvta.to.shared.u64 t, %1; cvt.u32.u64 %0, t; }" : "=r"(a) : "l"(p));
    return a;
}
__device__ __forceinline__ uint32_t pack_split(float x0, float x1, uint32_t& mid) {
    __nv_bfloat16 h0 = __float2bfloat16(x0);
    __nv_bfloat16 h1 = __float2bfloat16(x1);
    float r0 = x0 - __bfloat162float(h0);
    float r1 = x1 - __bfloat162float(h1);
    __nv_bfloat16 m0 = __float2bfloat16(r0);
    __nv_bfloat16 m1 = __float2bfloat16(r1);
    mid = ((uint32_t)__bfloat16_as_ushort(m1) << 16) | __bfloat16_as_ushort(m0);
    return ((uint32_t)__bfloat16_as_ushort(h1) << 16) | __bfloat16_as_ushort(h0);
}
__device__ __forceinline__ void ldm4(uint32_t& r0, uint32_t& r1, uint32_t& r2, uint32_t& r3,
                                     uint32_t addr) {
    asm volatile("ldmatrix.sync.aligned.m8n8.x4.shared.b16 {%0,%1,%2,%3}, [%4];"
                 : "=r"(r0), "=r"(r1), "=r"(r2), "=r"(r3) : "r"(addr));
}
__device__ __forceinline__ void mma16816(float* d, const uint32_t* a, uint32_t b0, uint32_t b1) {
    asm volatile("mma.sync.aligned.m16n8k16.row.col.f32.bf16.bf16.f32 "
                 "{%0,%1,%2,%3}, {%4,%5,%6,%7}, {%8,%9}, {%0,%1,%2,%3};"
                 : "+f"(d[0]), "+f"(d[1]), "+f"(d[2]), "+f"(d[3])
                 : "r"(a[0]), "r"(a[1]), "r"(a[2]), "r"(a[3]), "r"(b0), "r"(b1));
}

// ---------------- smem layout ----------------
constexpr int OFF_OM  = 0;          // NE*128*4 = 3072
constexpr int OFF_AH  = 3072;       // 128 x 80B
constexpr int OFF_AM  = 13312;
constexpr int OFF_B   = 23552;      // 3 stages x (BH 10240 | BM 10240)
constexpr int STAGE   = 20480;
constexpr int SMEM_BYTES = OFF_B + 3 * STAGE;   // 84992

// ---------------------------------------------------------------------------
// bf16x3 split GEMM on mma.sync, pipelined:
//   C[4096, Nw] = act( sum_e omega[:,e] * (A @ W_e) + bias )
// A split once per k-chunk (no omega); omega applied on register accumulators.
// B (pre-split bf16, [E][Nw][Kpad]) via 3-stage cp.async pipeline.
// ---------------------------------------------------------------------------
__global__ void __launch_bounds__(256, 1) gemm_mma(
    const float* __restrict__ A, int lda,
    const float* __restrict__ A2, int K1,
    const __nv_bfloat16* __restrict__ Wh, const __nv_bfloat16* __restrict__ Wm,
    const float* __restrict__ omega,
    const float* __restrict__ bias,
    float* __restrict__ C, int ldc,
    int Nw, int K, int Kpad, int E, int blend, int doElu)
{
    extern __shared__ char smem[];
    const uint32_t sb = smem_u32(smem);
    float* omS = (float*)(smem + OFF_OM);

    const int tid  = threadIdx.x;
    const int lane = tid & 31, warp = tid >> 5;
    const int m_base = (warp & 3) * 32;
    const int n_base = (warp >> 2) * 64;
    const int rowBase = blockIdx.y * 128;
    const int colBase = blockIdx.x * 128;

    for (int i = tid; i < E * 128; i += 256) {
        int e = i >> 7, r = i & 127;
        omS[e * 128 + r] = omega ? omega[(size_t)(rowBase + r) * E + e] : 1.0f;
    }

    float acc[2][8][4];
#pragma unroll
    for (int a = 0; a < 2; a++)
#pragma unroll
        for (int b = 0; b < 8; b++)
#pragma unroll
            for (int c = 0; c < 4; c++) acc[a][b][c] = 0.f;

    const int r  = tid >> 1, h = tid & 1;        // A staging: row, k-half
    const int row = rowBase + r;
    const int lm = lane & 15, lc = lane >> 4;    // ldmatrix A mapping
    const int g  = lane >> 3;
    const int b_row  = ((g >> 1) << 3) + (lane & 7);
    const int b_koff = (g & 1) << 4;

    const int nChunks = Kpad >> 5;
    const int NC = nChunks * E;

    // B stage issue: chunk c -> buffer c%3
    auto issue_stage = [&](int c) {
        const int e  = c % E;
        const int k0 = (c / E) << 5;
        const uint32_t base = sb + OFF_B + (c % 3) * STAGE;
#pragma unroll
        for (int q = 0; q < 4; q++) {
            int cl = tid + q * 256;              // 0..1023
            int bufsel = cl >> 9;
            int rem = cl & 511;
            int n = rem >> 2, j = rem & 3;
            int gn = colBase + n;
            const __nv_bfloat16* W = bufsel ? Wm : Wh;
            const char* src = (const char*)(W + ((size_t)e * Nw + (gn < Nw ? gn : 0)) * Kpad + k0) + j * 16;
            uint32_t dst = base + bufsel * 10240 + n * 80 + j * 16;
            int sz = (gn < Nw) ? 16 : 0;
            asm volatile("cp.async.cg.shared.global [%0], [%1], 16, %2;"
                         :: "r"(dst), "l"(src), "r"(sz));
        }
    };

    issue_stage(0);
    asm volatile("cp.async.commit_group;");
    issue_stage(1);
    asm volatile("cp.async.commit_group;");

    uint32_t aH[2][2][4], aM[2][2][4];           // [kh][mi2][4]

    for (int c = 0; c < NC; c++) {
        const int e = c % E;
        if (c < NC - 1) asm volatile("cp.async.wait_group 1;");
        else            asm volatile("cp.async.wait_group 0;");
        __syncthreads();

        if (e == 0) {
            // ---- A split for this k-chunk (no omega) ----
            const int k0 = (c / E) << 5;
            float v[16];
#pragma unroll
            for (int j = 0; j < 16; j++) {
                int k = k0 + h * 16 + j;
                float x = 0.f;
                if (k < K) x = (A2 && k >= K1) ? A2[row * 3 + (k - K1)]
                                               : A[(size_t)row * lda + k];
                v[j] = x;
            }
            uint32_t hi[8], mi[8];
#pragma unroll
            for (int u = 0; u < 8; u++) hi[u] = pack_split(v[2*u], v[2*u+1], mi[u]);
            char* dH = smem + OFF_AH + r * 80 + h * 32;
            char* dM = smem + OFF_AM + r * 80 + h * 32;
            *(uint4*)dH        = make_uint4(hi[0], hi[1], hi[2], hi[3]);
            *(uint4*)(dH + 16) = make_uint4(hi[4], hi[5], hi[6], hi[7]);
            *(uint4*)dM        = make_uint4(mi[0], mi[1], mi[2], mi[3]);
            *(uint4*)(dM + 16) = make_uint4(mi[4], mi[5], mi[6], mi[7]);
            __syncthreads();
            // ---- hoist A fragments into registers (reused across experts) ----
#pragma unroll
            for (int kh = 0; kh < 2; kh++)
#pragma unroll
                for (int m2 = 0; m2 < 2; m2++) {
                    uint32_t ad = (m_base + m2 * 16 + lm) * 80 + kh * 32 + lc * 16;
                    ldm4(aH[kh][m2][0], aH[kh][m2][1], aH[kh][m2][2], aH[kh][m2][3], sb + OFF_AH + ad);
                    ldm4(aM[kh][m2][0], aM[kh][m2][1], aM[kh][m2][2], aM[kh][m2][3], sb + OFF_AM + ad);
                }
        }

        // ---- MMA chunk into tmp, then omega-scale into acc ----
        float tmp[2][8][4];
#pragma unroll
        for (int a = 0; a < 2; a++)
#pragma unroll
            for (int b = 0; b < 8; b++)
#pragma unroll
                for (int cc = 0; cc < 4; cc++) tmp[a][b][cc] = 0.f;

        const uint32_t bhB = sb + OFF_B + (c % 3) * STAGE;
        const uint32_t bmB = bhB + 10240;
#pragma unroll
        for (int kh = 0; kh < 2; kh++) {
            uint32_t bh[4][4], bm[4][4];
#pragma unroll
            for (int ni = 0; ni < 4; ni++) {
                uint32_t bd = (n_base + ni * 16 + b_row) * 80 + kh * 32 + b_koff;
                ldm4(bh[ni][0], bh[ni][1], bh[ni][2], bh[ni][3], bhB + bd);
                ldm4(bm[ni][0], bm[ni][1], bm[ni][2], bm[ni][3], bmB + bd);
            }
#pragma unroll
            for (int ni = 0; ni < 4; ni++)
#pragma unroll
                for (int m2 = 0; m2 < 2; m2++) {
                    mma16816(tmp[m2][2*ni],   aH[kh][m2], bh[ni][0], bh[ni][1]);  // hi*hi
                    mma16816(tmp[m2][2*ni+1], aH[kh][m2], bh[ni][2], bh[ni][3]);
                    mma16816(tmp[m2][2*ni],   aH[kh][m2], bm[ni][0], bm[ni][1]);  // hi*mid
                    mma16816(tmp[m2][2*ni+1], aH[kh][m2], bm[ni][2], bm[ni][3]);
                    mma16816(tmp[m2][2*ni],   aM[kh][m2], bh[ni][0], bh[ni][1]);  // mid*hi
                    mma16816(tmp[m2][2*ni+1], aM[kh][m2], bh[ni][2], bh[ni][3]);
                }
        }
#pragma unroll
        for (int m2 = 0; m2 < 2; m2++) {
            float wA = omS[e * 128 + m_base + m2 * 16 + (lane >> 2)];
            float wB = omS[e * 128 + m_base + m2 * 16 + (lane >> 2) + 8];
#pragma unroll
            for (int nj = 0; nj < 8; nj++) {
                acc[m2][nj][0] += wA * tmp[m2][nj][0];
                acc[m2][nj][1] += wA * tmp[m2][nj][1];
                acc[m2][nj][2] += wB * tmp[m2][nj][2];
                acc[m2][nj][3] += wB * tmp[m2][nj][3];
            }
        }

        if (c + 2 < NC) issue_stage(c + 2);
        asm volatile("cp.async.commit_group;");
    }

    // ---- epilogue ----
#pragma unroll
    for (int m2 = 0; m2 < 2; m2++) {
        int rlA = m_base + m2 * 16 + (lane >> 2);
        int rlB = rlA + 8;
#pragma unroll
        for (int nj = 0; nj < 8; nj++) {
            int n = colBase + n_base + nj * 8 + ((lane & 3) << 1);
            if (n >= Nw) continue;
            float bA0, bA1, bB0, bB1;
            if (blend) {
                bA0 = bA1 = bB0 = bB1 = 0.f;
                for (int e = 0; e < NE; e++) {
                    float be0 = bias[e * Nw + n], be1 = bias[e * Nw + n + 1];
                    bA0 += omS[e * 128 + rlA] * be0;  bA1 += omS[e * 128 + rlA] * be1;
                    bB0 += omS[e * 128 + rlB] * be0;  bB1 += omS[e * 128 + rlB] * be1;
                }
            } else {
                bA0 = bB0 = bias[n];
                bA1 = bB1 = bias[n + 1];
            }
            float v0 = acc[m2][nj][0] + bA0, v1 = acc[m2][nj][1] + bA1;
            float v2 = acc[m2][nj][2] + bB0, v3 = acc[m2][nj][3] + bB1;
            if (doElu) { v0 = elu1(v0); v1 = elu1(v1); v2 = elu1(v2); v3 = elu1(v3); }
            *(float2*)&C[(size_t)(rowBase + rlA) * ldc + n] = make_float2(v0, v1);
            *(float2*)&C[(size_t)(rowBase + rlB) * ldc + n] = make_float2(v2, v3);
        }
    }
}

// ---------------------------------------------------------------------------
// Weight prep: transpose [K,N] fp32 -> [N,Kpad] bf16 hi/mid (zero pad)
// ---------------------------------------------------------------------------
__global__ void prep_split(const float* __restrict__ W, __nv_bfloat16* __restrict__ oh,
                           __nv_bfloat16* __restrict__ om_, int K, int Nw, int Kpad) {
    __shared__ float t[32][33];
    int e = blockIdx.z;
    const float* Ws = W + (size_t)e * K * Nw;
    __nv_bfloat16* po = oh  + (size_t)e * Nw * Kpad;
    __nv_bfloat16* pm = om_ + (size_t)e * Nw * Kpad;
    int k0 = blockIdx.x * 32, n0 = blockIdx.y * 32;
    int tx = threadIdx.x, ty = threadIdx.y;
#pragma unroll
    for (int i = 0; i < 4; i++) {
        int kk = k0 + ty + i * 8, nn = n0 + tx;
        t[ty + i * 8][tx] = (kk < K && nn < Nw) ? Ws[(size_t)kk * Nw + nn] : 0.f;
    }
    __syncthreads();
#pragma unroll
    for (int i = 0; i < 4; i++) {
        int nn = n0 + ty + i * 8, kk = k0 + tx;
        if (nn < Nw) {
            float x = t[tx][ty + i * 8];
            __nv_bfloat16 hh = __float2bfloat16(x);
            __nv_bfloat16 mm = __float2bfloat16(x - __bfloat162float(hh));
            po[(size_t)nn * Kpad + kk] = hh;
            pm[(size_t)nn * Kpad + kk] = mm;
        }
    }
}

__device__ __forceinline__ float head_w(const float* pw, const float* tw,
                                        const float* dw, const float* vw, int k, int n) {
    if (n < 330) return pw[k * 330 + n];
    if (n < 333) return tw[k * 3 + (n - 330)];
    if (n < 630) return dw[k * 297 + (n - 333)];
    return vw[(size_t)k * 1200 + (n - 630)];
}
__global__ void prep_heads(const float* pw, const float* tw, const float* dw, const float* vw,
                           __nv_bfloat16* oh, __nv_bfloat16* om_) {
    __shared__ float t[32][33];
    int k0 = blockIdx.x * 32, n0 = blockIdx.y * 32;
    int tx = threadIdx.x, ty = threadIdx.y;
#pragma unroll
    for (int i = 0; i < 4; i++) {
        int kk = k0 + ty + i * 8, nn = n0 + tx;
        t[ty + i * 8][tx] = (kk < 512 && nn < DF) ? head_w(pw, tw, dw, vw, kk, nn) : 0.f;
    }
    __syncthreads();
#pragma unroll
    for (int i = 0; i < 4; i++) {
        int nn = n0 + ty + i * 8, kk = k0 + tx;
        if (nn < DF) {
            float x = t[tx][ty + i * 8];
            __nv_bfloat16 hh = __float2bfloat16(x);
            __nv_bfloat16 mm = __float2bfloat16(x - __bfloat162float(hh));
            oh[(size_t)nn * 512 + kk] = hh;
            om_[(size_t)nn * 512 + kk] = mm;
        }
    }
}
__global__ void prep_hbias(const float* pb, const float* tb, const float* db, const float* vb,
                           float* out) {
    int n = blockIdx.x * 256 + threadIdx.x;
    if (n >= DF) return;
    float v;
    if (n < 330) v = pb[n];
    else if (n < 333) v = tb[n - 330];
    else if (n < 630) v = db[n - 333];
    else v = vb[n - 630];
    out[n] = v;
}

// ---------------------------------------------------------------------------
__global__ void assemble_frame(const float* __restrict__ rot, const float* __restrict__ tr,
                               const float* __restrict__ verts, const float* __restrict__ dists) {
    int idx = blockIdx.x * 256 + threadIdx.x;
    if (idx >= BSZ * DF) return;
    int b = idx / DF, c = idx % DF;
    float v;
    if (c < 330) {
        int j = c / 6, s = c % 6;
        v = rot[b * 495 + j * 9 + (s >> 1) * 3 + (s & 1)];
    } else if (c < 333) v = tr[b * 3 + (c - 330)];
    else if (c < 1533)  v = verts[b * 1200 + (c - 333)];
    else                v = dists[b * 297 + (c - 1533)];
    g_h0[(size_t)b * DPD + c] = v;
}

__global__ void gate3_softmax(const float* __restrict__ H, const float* __restrict__ W,
                              const float* __restrict__ b, float* __restrict__ om) {
    int warp = (blockIdx.x * blockDim.x + threadIdx.x) >> 5;
    int lane = threadIdx.x & 31;
    if (warp >= BSZ) return;
    float p[NE] = {};
    for (int k = lane; k < 256; k += 32) {
        float x = H[(size_t)warp * 256 + k];
#pragma unroll
        for (int e = 0; e < NE; e++) p[e] += x * W[k * NE + e];
    }
#pragma unroll
    for (int e = 0; e < NE; e++)
        for (int o = 16; o > 0; o >>= 1) p[e] += __shfl_down_sync(0xffffffffu, p[e], o);
    if (lane == 0) {
        float m = -1e30f;
#pragma unroll
        for (int e = 0; e < NE; e++) { p[e] += b[e]; m = fmaxf(m, p[e]); }
        float s = 0.f;
#pragma unroll
        for (int e = 0; e < NE; e++) { p[e] = expf(p[e] - m); s += p[e]; }
        float inv = 1.f / s;
#pragma unroll
        for (int e = 0; e < NE; e++) om[(size_t)warp * NE + e] = p[e] * inv;
    }
}

__global__ void post_pose(const float* __restrict__ hd, float* __restrict__ out) {
    int idx = blockIdx.x * 256 + threadIdx.x;
    if (idx >= BSZ * 55) return;
    int b = idx / 55, j = idx % 55;
    const float* p = hd + (size_t)b * DF + j * 6;
    float a1x = p[0], a2x = p[1], a1y = p[2], a2y = p[3], a1z = p[4], a2z = p[5];
    float inv = rsqrtf(a1x * a1x + a1y * a1y + a1z * a1z);
    float b1x = a1x * inv, b1y = a1y * inv, b1z = a1z * inv;
    float d = b1x * a2x + b1y * a2y + b1z * a2z;
    float cx = a2x - d * b1x, cy = a2y - d * b1y, cz = a2z - d * b1z;
    float inv2 = rsqrtf(cx * cx + cy * cy + cz * cz);
    float b2x = cx * inv2, b2y = cy * inv2, b2z = cz * inv2;
    float b3x = b1y * b2z - b1z * b2y;
    float b3y = b1z * b2x - b1x * b2z;
    float b3z = b1x * b2y - b1y * b2x;
    float* o = out + (size_t)b * 495 + j * 9;
    o[0] = b1x; o[1] = b2x; o[2] = b3x;
    o[3] = b1y; o[4] = b2y; o[5] = b3y;
    o[6] = b1z; o[7] = b2z; o[8] = b3z;
}

__global__ void post_copy(const float* __restrict__ hd, float* __restrict__ out) {
    const size_t base_t = (size_t)BSZ * 495;
    const size_t base_d = base_t + (size_t)BSZ * 3;
    const size_t base_v = base_d + (size_t)BSZ * 297;
    int idx = blockIdx.x * 256 + threadIdx.x;
    if (idx >= BSZ * 1500) return;
    int b = idx / 1500, c = idx % 1500;
    const float* row = hd + (size_t)b * DF;
    if (c < 3)        out[base_t + (size_t)b * 3 + c]            = row[330 + c];
    else if (c < 300) out[base_d + (size_t)b * 297 + (c - 3)]    = row[333 + (c - 3)];
    else              out[base_v + (size_t)b * 1200 + (c - 300)] = row[630 + (c - 300)];
}

// ---------------------------------------------------------------------------
extern "C" void kernel_launch(void* const* d_in, const int* in_sizes, int n_in,
                              void* d_out, int out_size) {
    const float* rot   = (const float*)d_in[0];
    const float* tr    = (const float*)d_in[1];
    const float* verts = (const float*)d_in[2];
    const float* dists = (const float*)d_in[3];
    const float* bps   = (const float*)d_in[4];
    const float* ogt   = (const float*)d_in[5];
    const float* iw1 = (const float*)d_in[6];  const float* ib1 = (const float*)d_in[7];
    const float* iw2 = (const float*)d_in[8];  const float* ib2 = (const float*)d_in[9];
    const float* iw3 = (const float*)d_in[10]; const float* ib3 = (const float*)d_in[11];
    const float* gw1 = (const float*)d_in[12]; const float* gb1 = (const float*)d_in[13];
    const float* gw2 = (const float*)d_in[14]; const float* gb2 = (const float*)d_in[15];
    const float* gw3 = (const float*)d_in[16]; const float* gb3 = (const float*)d_in[17];
    const float* ew1 = (const float*)d_in[18]; const float* eb1 = (const float*)d_in[19];
    const float* ew2 = (const float*)d_in[20]; const float* eb2 = (const float*)d_in[21];
    const float* ew3 = (const float*)d_in[22]; const float* eb3 = (const float*)d_in[23];
    const float* pw  = (const float*)d_in[24]; const float* pb  = (const float*)d_in[25];
    const float* tw  = (const float*)d_in[26]; const float* tb  = (const float*)d_in[27];
    const float* vw  = (const float*)d_in[28]; const float* vb  = (const float*)d_in[29];
    const float* dw  = (const float*)d_in[30]; const float* db  = (const float*)d_in[31];
    float* out = (float*)d_out;

    cudaFuncSetAttribute(gemm_mma, cudaFuncAttributeMaxDynamicSharedMemorySize, SMEM_BYTES);

    float *h0, *ih1, *ih2, *gh1, *gh2, *om, *e1, *e2, *e3, *hd, *hbias;
    cudaGetSymbolAddress((void**)&h0,  g_h0);
    cudaGetSymbolAddress((void**)&ih1, g_ih1);
    cudaGetSymbolAddress((void**)&ih2, g_ih2);
    cudaGetSymbolAddress((void**)&gh1, g_gh1);
    cudaGetSymbolAddress((void**)&gh2, g_gh2);
    cudaGetSymbolAddress((void**)&om,  g_om);
    cudaGetSymbolAddress((void**)&e1,  g_e1);
    cudaGetSymbolAddress((void**)&e2,  g_e2);
    cudaGetSymbolAddress((void**)&e3,  g_e3);
    cudaGetSymbolAddress((void**)&hd,  g_hd);
    cudaGetSymbolAddress((void**)&hbias, g_hbias);
    __nv_bfloat16 *iw1h,*iw1m,*iw2h,*iw2m,*iw3h,*iw3m,*gw1h,*gw1m,*gw2h,*gw2m;
    __nv_bfloat16 *ew1h,*ew1m,*ew2h,*ew2m,*ew3h,*ew3m,*hwh,*hwm;
    cudaGetSymbolAddress((void**)&iw1h, s_iw1h); cudaGetSymbolAddress((void**)&iw1m, s_iw1m);
    cudaGetSymbolAddress((void**)&iw2h, s_iw2h); cudaGetSymbolAddress((void**)&iw2m, s_iw2m);
    cudaGetSymbolAddress((void**)&iw3h, s_iw3h); cudaGetSymbolAddress((void**)&iw3m, s_iw3m);
    cudaGetSymbolAddress((void**)&gw1h, s_gw1h); cudaGetSymbolAddress((void**)&gw1m, s_gw1m);
    cudaGetSymbolAddress((void**)&gw2h, s_gw2h); cudaGetSymbolAddress((void**)&gw2m, s_gw2m);
    cudaGetSymbolAddress((void**)&ew1h, s_ew1h); cudaGetSymbolAddress((void**)&ew1m, s_ew1m);
    cudaGetSymbolAddress((void**)&ew2h, s_ew2h); cudaGetSymbolAddress((void**)&ew2m, s_ew2m);
    cudaGetSymbolAddress((void**)&ew3h, s_ew3h); cudaGetSymbolAddress((void**)&ew3m, s_ew3m);
    cudaGetSymbolAddress((void**)&hwh,  s_hwh);  cudaGetSymbolAddress((void**)&hwm,  s_hwm);

    dim3 tb32(32, 8);
    prep_split<<<dim3(KP_I1/32, 8, 1),  tb32>>>(iw1, iw1h, iw1m, 1027, 256, KP_I1);
    prep_split<<<dim3(8, 8, 1),         tb32>>>(iw2, iw2h, iw2m, 256, 256, 256);
    prep_split<<<dim3(8, 8, 1),         tb32>>>(iw3, iw3h, iw3m, 256, 256, 256);
    prep_split<<<dim3(KP_G1/32, 16, 1), tb32>>>(gw1, gw1h, gw1m, 1830, 512, KP_G1);
    prep_split<<<dim3(16, 8, 1),        tb32>>>(gw2, gw2h, gw2m, 512, 256, 512);
    prep_split<<<dim3(KP_E1/32, 16, NE),tb32>>>(ew1, ew1h, ew1m, 2086, 512, KP_E1);
    prep_split<<<dim3(16, 16, NE),      tb32>>>(ew2, ew2h, ew2m, 512, 512, 512);
    prep_split<<<dim3(16, 16, NE),      tb32>>>(ew3, ew3h, ew3m, 512, 512, 512);
    prep_heads<<<dim3(16, 58, 1),       tb32>>>(pw, tw, dw, vw, hwh, hwm);
    prep_hbias<<<8, 256>>>(pb, tb, db, vb, hbias);

    assemble_frame<<<(BSZ * DF + 255) / 256, 256>>>(rot, tr, verts, dists);

    const int GY = BSZ / 128;  // 32
    gemm_mma<<<dim3(2, GY), 256, SMEM_BYTES>>>(bps, 1024, ogt, 1024, iw1h, iw1m, nullptr, ib1,
                                               ih1, 256, 256, 1027, KP_I1, 1, 0, 1);
    gemm_mma<<<dim3(2, GY), 256, SMEM_BYTES>>>(ih1, 256, nullptr, 0, iw2h, iw2m, nullptr, ib2,
                                               ih2, 256, 256, 256, 256, 1, 0, 1);
    gemm_mma<<<dim3(2, GY), 256, SMEM_BYTES>>>(ih2, 256, nullptr, 0, iw3h, iw3m, nullptr, ib3,
                                               h0 + 1830, DPD, 256, 256, 256, 1, 0, 1);
    gemm_mma<<<dim3(4, GY), 256, SMEM_BYTES>>>(h0, DPD, nullptr, 0, gw1h, gw1m, nullptr, gb1,
                                               gh1, 512, 512, 1830, KP_G1, 1, 0, 1);
    gemm_mma<<<dim3(2, GY), 256, SMEM_BYTES>>>(gh1, 512, nullptr, 0, gw2h, gw2m, nullptr, gb2,
                                               gh2, 256, 256, 512, 512, 1, 0, 1);
    gate3_softmax<<<BSZ / 8, 256>>>(gh2, gw3, gb3, om);
    gemm_mma<<<dim3(4, GY), 256, SMEM_BYTES>>>(h0, DPD, nullptr, 0, ew1h, ew1m, om, eb1,
                                               e1, DH, DH, DPD, KP_E1, NE, 1, 1);
    gemm_mma<<<dim3(4, GY), 256, SMEM_BYTES>>>(e1, DH, nullptr, 0, ew2h, ew2m, om, eb2,
                                               e2, DH, DH, DH, DH, NE, 1, 1);
    gemm_mma<<<dim3(4, GY), 256, SMEM_BYTES>>>(e2, DH, nullptr, 0, ew3h, ew3m, om, eb3,
                                               e3, DH, DH, DH, DH, NE, 1, 1);
    gemm_mma<<<dim3(15, GY), 256, SMEM_BYTES>>>(e3, DH, nullptr, 0, hwh, hwm, nullptr, hbias,
                                                hd, DF, DF, DH, DH, 1, 0, 0);
    post_pose<<<(BSZ * 55 + 255) / 256, 256>>>(hd, out);
    post_copy<<<(BSZ * 1500 + 255) / 256, 256>>>(hd, out);
}